// round 16
// baseline (speedup 1.0000x reference)
#include <cuda_runtime.h>
#include <math.h>

// ---------------- problem constants ----------------
#define Bn   32
#define Ln   256
#define Dd   768
#define ATT  100
#define Hh   5
#define DK   20
#define NROW (Bn*Ln)            // 8192

// ---------------- scratch ----------------
#define OFF_G     6291456ll
#define OFF_Q     7110656ll
#define OFF_K     7929856ll
#define OFF_GO    8749056ll
#define OFF_HS0   11206656ll    // 32*256*256
#define OFF_HSW   13303808ll    // 32*256*256 (contiguous after HS0)
#define OFF_ASP   23792768ll    // 32*20
#define OFF_SG1   23834368ll    // 8192
#define OFF_SG2   23875328ll
#define OFF_AX    23916288ll    // 4 * 8192*100 partial Ax
#define SCRATCH_TOTAL 27193088ll

__device__ __align__(16) float d_scratch[SCRATCH_TOTAL];

// =====================================================================
// 1. Fused LayerNorm + GEMM:  g = LN(x) @ Wxx_w + Wxx_b
//    (R15 + single-sync double buffering)
// =====================================================================
__global__ __launch_bounds__(320, 3)
void lng_kernel(const float* __restrict__ x,
                const float* __restrict__ ga,
                const float* __restrict__ gb,
                const float* __restrict__ Ww,
                const float* __restrict__ Wb,
                float* __restrict__ g) {
    __shared__ __align__(16) float As[2][16][36];
    __shared__ __align__(16) float Bs[2][16][104];
    __shared__ float smean[32], sinv[32];

    int tid = threadIdx.x;
    int m0 = blockIdx.x * 32;
    int w = tid >> 5, lane = tid & 31;

    if (w < 8) {
        #pragma unroll
        for (int r = 0; r < 4; r++) {
            int row = w * 4 + r;
            const float4* xr = reinterpret_cast<const float4*>(x + (long long)(m0 + row) * Dd);
            float sum = 0.f, sq = 0.f;
            #pragma unroll
            for (int i = 0; i < 6; i++) {
                float4 v = xr[lane + i * 32];
                sum += v.x + v.y + v.z + v.w;
                sq  += v.x*v.x + v.y*v.y + v.z*v.z + v.w*v.w;
            }
            #pragma unroll
            for (int o = 16; o > 0; o >>= 1) {
                sum += __shfl_xor_sync(0xffffffffu, sum, o);
                sq  += __shfl_xor_sync(0xffffffffu, sq,  o);
            }
            if (lane == 0) {
                float mean = sum * (1.f / (float)Dd);
                float var = (sq - (float)Dd * mean * mean) * (1.f / (float)(Dd - 1));
                smean[row] = mean;
                sinv[row] = 1.f / (sqrtf(var) + 1e-6f);
            }
        }
    }
    __syncthreads();

    int tx = tid % 20, ty = tid / 20;
    int tx5 = tx * 5, ty2 = ty * 2;

    bool aok = (tid < 128);
    int ar = tid >> 2, ac = (tid & 3) << 2;
    int b0r = tid / 25, b0c = (tid % 25) * 4;
    int bi1 = tid + 320;
    bool b1ok = (bi1 < 400);
    int b1r = bi1 / 25, b1c = (bi1 % 25) * 4;

    const float* Xrow = x + (long long)(m0 + ar) * Dd;
    float meanv = 0.f, invv = 0.f;
    if (aok) { meanv = smean[ar]; invv = sinv[ar]; }

    float acc[2][5];
    #pragma unroll
    for (int i = 0; i < 2; i++)
        #pragma unroll
        for (int j = 0; j < 5; j++) acc[i][j] = 0.f;

    float4 aR = make_float4(0.f,0.f,0.f,0.f), bR0 = aR, bR1 = aR;

    #define LOAD_LNA(k0)                                                 \
        do {                                                             \
            float4 x4 = *reinterpret_cast<const float4*>(Xrow + (k0) + ac);   \
            float4 ga4 = *reinterpret_cast<const float4*>(ga + (k0) + ac);    \
            float4 gb4 = *reinterpret_cast<const float4*>(gb + (k0) + ac);    \
            aR.x = ga4.x * (x4.x - meanv) * invv + gb4.x;                \
            aR.y = ga4.y * (x4.y - meanv) * invv + gb4.y;                \
            aR.z = ga4.z * (x4.z - meanv) * invv + gb4.z;                \
            aR.w = ga4.w * (x4.w - meanv) * invv + gb4.w;                \
        } while (0)

    if (aok) LOAD_LNA(0);
    bR0 = *reinterpret_cast<const float4*>(Ww + (long long)b0r * ATT + b0c);
    if (b1ok) bR1 = *reinterpret_cast<const float4*>(Ww + (long long)b1r * ATT + b1c);

    int s = 0;
    for (int t = 0; t < 48; t++) {
        if (aok) {
            As[s][ac + 0][ar] = aR.x;
            As[s][ac + 1][ar] = aR.y;
            As[s][ac + 2][ar] = aR.z;
            As[s][ac + 3][ar] = aR.w;
        }
        *reinterpret_cast<float4*>(&Bs[s][b0r][b0c]) = bR0;
        if (b1ok) *reinterpret_cast<float4*>(&Bs[s][b1r][b1c]) = bR1;
        __syncthreads();
        if (t + 1 < 48) {
            int k0 = (t + 1) * 16;
            if (aok) LOAD_LNA(k0);
            bR0 = *reinterpret_cast<const float4*>(Ww + (long long)(k0 + b0r) * ATT + b0c);
            if (b1ok) bR1 = *reinterpret_cast<const float4*>(Ww + (long long)(k0 + b1r) * ATT + b1c);
        }
        #pragma unroll
        for (int kk = 0; kk < 16; kk++) {
            float a0 = As[s][kk][ty2 + 0];
            float a1 = As[s][kk][ty2 + 1];
            float b0 = Bs[s][kk][tx5 + 0];
            float b1 = Bs[s][kk][tx5 + 1];
            float b2 = Bs[s][kk][tx5 + 2];
            float b3 = Bs[s][kk][tx5 + 3];
            float b4 = Bs[s][kk][tx5 + 4];
            acc[0][0] += a0*b0; acc[0][1] += a0*b1; acc[0][2] += a0*b2; acc[0][3] += a0*b3; acc[0][4] += a0*b4;
            acc[1][0] += a1*b0; acc[1][1] += a1*b1; acc[1][2] += a1*b2; acc[1][3] += a1*b3; acc[1][4] += a1*b4;
        }
        s ^= 1;   // single-sync double buffering
    }
    #undef LOAD_LNA

    float wb[5];
    #pragma unroll
    for (int j = 0; j < 5; j++) wb[j] = Wb[tx5 + j];
    #pragma unroll
    for (int i = 0; i < 2; i++) {
        float* crow = g + (long long)(m0 + ty2 + i) * ATT;
        #pragma unroll
        for (int j = 0; j < 5; j++) crow[tx5 + j] = acc[i][j] + wb[j];
    }
}

// =====================================================================
// 2. Merged: q/k projections + aspect pooling (R15 + single-sync)
// =====================================================================
__global__ __launch_bounds__(320, 2)
void qkaspect_kernel(const float* __restrict__ g,
                     const float* __restrict__ q_w, const float* __restrict__ q_b,
                     const float* __restrict__ k_w, const float* __restrict__ k_b,
                     const float* __restrict__ amask,
                     const float* __restrict__ dense_w,
                     const float* __restrict__ dense_b,
                     float* __restrict__ q, float* __restrict__ k,
                     float* __restrict__ asp) {
    int blk = blockIdx.x;
    int tid = threadIdx.x;

    if (blk < 256) {
        __shared__ __align__(16) float As[2][20][68];
        __shared__ __align__(16) float Bs[2][20][104];

        const float* Bw; const float* bias; float* C;
        if (blk < 128) { Bw = q_w; bias = q_b; C = q; }
        else           { Bw = k_w; bias = k_b; C = k; }
        int m0 = (blk & 127) * 64;

        int tx = tid % 20, ty = tid / 20;
        int tx5 = tx * 5, ty4 = ty * 4;

        int ar = tid / 5, ac = (tid % 5) * 4;
        int b0r = tid / 25, b0c = (tid % 25) * 4;
        int bi1 = tid + 320;
        bool b1ok = (bi1 < 500);
        int b1r = bi1 / 25, b1c = (bi1 % 25) * 4;

        const float* Arow = g + (long long)(m0 + ar) * ATT;

        float acc[4][5];
        #pragma unroll
        for (int i = 0; i < 4; i++)
            #pragma unroll
            for (int j = 0; j < 5; j++) acc[i][j] = 0.f;

        float4 aR, bR0, bR1 = make_float4(0.f,0.f,0.f,0.f);
        aR = *reinterpret_cast<const float4*>(Arow + ac);
        bR0 = *reinterpret_cast<const float4*>(Bw + (long long)b0r * ATT + b0c);
        if (b1ok) bR1 = *reinterpret_cast<const float4*>(Bw + (long long)b1r * ATT + b1c);

        int s = 0;
        for (int t = 0; t < 5; t++) {
            As[s][ac + 0][ar] = aR.x;
            As[s][ac + 1][ar] = aR.y;
            As[s][ac + 2][ar] = aR.z;
            As[s][ac + 3][ar] = aR.w;
            *reinterpret_cast<float4*>(&Bs[s][b0r][b0c]) = bR0;
            if (b1ok) *reinterpret_cast<float4*>(&Bs[s][b1r][b1c]) = bR1;
            __syncthreads();
            if (t + 1 < 5) {
                int k0 = (t + 1) * 20;
                aR = *reinterpret_cast<const float4*>(Arow + k0 + ac);
                bR0 = *reinterpret_cast<const float4*>(Bw + (long long)(k0 + b0r) * ATT + b0c);
                if (b1ok) bR1 = *reinterpret_cast<const float4*>(Bw + (long long)(k0 + b1r) * ATT + b1c);
            }
            #pragma unroll
            for (int kk = 0; kk < 20; kk++) {
                float4 a4 = *reinterpret_cast<const float4*>(&As[s][kk][ty4]);
                float b0 = Bs[s][kk][tx5 + 0];
                float b1 = Bs[s][kk][tx5 + 1];
                float b2 = Bs[s][kk][tx5 + 2];
                float b3 = Bs[s][kk][tx5 + 3];
                float b4 = Bs[s][kk][tx5 + 4];
                acc[0][0] += a4.x*b0; acc[0][1] += a4.x*b1; acc[0][2] += a4.x*b2; acc[0][3] += a4.x*b3; acc[0][4] += a4.x*b4;
                acc[1][0] += a4.y*b0; acc[1][1] += a4.y*b1; acc[1][2] += a4.y*b2; acc[1][3] += a4.y*b3; acc[1][4] += a4.y*b4;
                acc[2][0] += a4.z*b0; acc[2][1] += a4.z*b1; acc[2][2] += a4.z*b2; acc[2][3] += a4.z*b3; acc[2][4] += a4.z*b4;
                acc[3][0] += a4.w*b0; acc[3][1] += a4.w*b1; acc[3][2] += a4.w*b2; acc[3][3] += a4.w*b3; acc[3][4] += a4.w*b4;
            }
            s ^= 1;   // single-sync double buffering
        }

        float wb[5];
        #pragma unroll
        for (int j = 0; j < 5; j++) wb[j] = bias[tx5 + j];
        #pragma unroll
        for (int i = 0; i < 4; i++) {
            float* crow = C + (long long)(m0 + ty4 + i) * ATT;
            #pragma unroll
            for (int j = 0; j < 5; j++) crow[tx5 + j] = acc[i][j] + wb[j];
        }
    } else {
        int b = blk - 256;
        int w = tid >> 5, lane = tid & 31;
        __shared__ float smask[Ln];
        __shared__ float part[8][104];
        __shared__ float sa[104];
        __shared__ float wred[8];

        if (tid < 256) smask[tid] = amask[b * Ln + tid];
        __syncthreads();

        if (w < 8) {
            float acc[4] = {0.f, 0.f, 0.f, 0.f};
            float wsum = 0.f;
            const float* gb_ = g + (long long)b * Ln * ATT;
            for (int i = w * 32; i < w * 32 + 32; i++) {
                float m = smask[i];
                wsum += m;
                const float* gr = gb_ + (long long)i * ATT;
                #pragma unroll
                for (int c4 = 0; c4 < 4; c4++) {
                    int c = lane + c4 * 32;
                    float gv = (c < ATT) ? gr[c] : 0.f;
                    acc[c4] += gv * m;
                }
            }
            #pragma unroll
            for (int c4 = 0; c4 < 4; c4++) {
                int c = lane + c4 * 32;
                if (c < ATT) part[w][c] = acc[c4];
            }
            if (lane == 0) wred[w] = wsum;
        }
        __syncthreads();
        if (tid < ATT) {
            float s = 0.f;
            #pragma unroll
            for (int ww = 0; ww < 8; ww++) s += part[ww][tid];
            sa[tid] = s;
        }
        if (tid == 0) {
            float s = 0.f;
            #pragma unroll
            for (int ww = 0; ww < 8; ww++) s += wred[ww];
            wred[0] = 1.f / s;
        }
        __syncthreads();
        float inv = wred[0];
        if (tid < DK) {
            float s = dense_b[tid];
            for (int c = 0; c < ATT; c++) s += sa[c] * inv * dense_w[c * DK + tid];
            asp[b * DK + tid] = s;
        }
    }
}

// =====================================================================
// 3. scores: 16 rows/CTA, per-(b,h), atomic h-reduced maps.
//    addv computed inline pre-barrier (own kt row + gmem-broadcast asp);
//    src_mask penalty folded into addv (no msk smem, no inner predicate).
//    Single barrier total.
// =====================================================================
__global__ __launch_bounds__(256, 4)
void scores_kernel(const float* __restrict__ q,
                   const float* __restrict__ k,
                   const float* __restrict__ asp,
                   const float* __restrict__ bias_m,
                   const int*   __restrict__ src_mask,
                   const float* __restrict__ short_mask,
                   const float* __restrict__ Wx_w,
                   const float* __restrict__ clf_b,
                   float* __restrict__ hs0,
                   float* __restrict__ hsw,
                   float* __restrict__ out) {
    int it = blockIdx.x, h = blockIdx.y, b = blockIdx.z;
    __shared__ float kt[Ln][21];
    __shared__ float addv[Ln];
    __shared__ float qs[16][20];
    int t = threadIdx.x, w = t >> 5, lane = t & 31;
    int i0 = it * 16 + w * 2;

    if (it == 0 && h == 0 && t < 3) out[b * 3 + t] = clf_b[t];

    // K row t (head-h slice) -> smem, keep in registers for addv
    float kreg[20];
    {
        const float4* kr = reinterpret_cast<const float4*>(
            k + ((long long)b * Ln + t) * ATT + h * DK);
        #pragma unroll
        for (int f = 0; f < 5; f++) {
            float4 v = kr[f];
            kreg[f * 4 + 0] = v.x;
            kreg[f * 4 + 1] = v.y;
            kreg[f * 4 + 2] = v.z;
            kreg[f * 4 + 3] = v.w;
            kt[t][f * 4 + 0] = v.x;
            kt[t][f * 4 + 1] = v.y;
            kt[t][f * 4 + 2] = v.z;
            kt[t][f * 4 + 3] = v.w;
        }
    }
    for (int idx = t; idx < 16 * DK; idx += 256) {
        int r = idx / DK, d = idx % DK;
        qs[r][d] = q[((long long)b * Ln + it * 16 + r) * ATT + h * DK + d];
    }
    // addv[t]: asp read via broadcast LDG (no smem ordering hazard);
    // mask penalty folded in.
    {
        const float* aspb = asp + b * DK;
        float s = 0.f;
        #pragma unroll
        for (int d = 0; d < DK; d++) s += aspb[d] * kreg[d];
        float mpen = (src_mask[b * Ln + t] == 0) ? -1e9f : 0.f;
        addv[t] = tanhf(s + bias_m[0]) + mpen;
    }
    __syncthreads();   // single barrier

    float wsh = 0.f;
    #pragma unroll
    for (int kk = 0; kk < 5; kk++) wsh += Wx_w[h * 5 + kk];

    float smr[2][8];
    #pragma unroll
    for (int r = 0; r < 2; r++) {
        const float* srow = short_mask + ((long long)b * Ln + i0 + r) * Ln;
        #pragma unroll
        for (int jj = 0; jj < 8; jj++) smr[r][jj] = srow[lane + jj * 32];
    }

    float sc[2][8];
    #pragma unroll
    for (int r = 0; r < 2; r++)
        #pragma unroll
        for (int jj = 0; jj < 8; jj++) sc[r][jj] = 0.f;

    #pragma unroll
    for (int d = 0; d < DK; d++) {
        float qd0 = qs[w * 2 + 0][d];
        float qd1 = qs[w * 2 + 1][d];
        #pragma unroll
        for (int jj = 0; jj < 8; jj++) {
            float kv = kt[lane + jj * 32][d];
            sc[0][jj] += qd0 * kv;
            sc[1][jj] += qd1 * kv;
        }
    }

    const float rsd = 0.22360679774997896f;
    #pragma unroll
    for (int r = 0; r < 2; r++) {
        float mx = -3.4e38f;
        #pragma unroll
        for (int jj = 0; jj < 8; jj++) {
            int j = lane + jj * 32;
            float v = sc[r][jj] * rsd + addv[j] + smr[r][jj];
            sc[r][jj] = v;
            mx = fmaxf(mx, v);
        }
        #pragma unroll
        for (int o = 16; o > 0; o >>= 1) mx = fmaxf(mx, __shfl_xor_sync(0xffffffffu, mx, o));
        float sum = 0.f;
        #pragma unroll
        for (int jj = 0; jj < 8; jj++) { sc[r][jj] = expf(sc[r][jj] - mx); sum += sc[r][jj]; }
        #pragma unroll
        for (int o = 16; o > 0; o >>= 1) sum += __shfl_xor_sync(0xffffffffu, sum, o);
        float invs = 1.f / sum;
        float* r0 = hs0 + ((long long)b * Ln + i0 + r) * Ln;
        float* rw = hsw + ((long long)b * Ln + i0 + r) * Ln;
        #pragma unroll
        for (int jj = 0; jj < 8; jj++) {
            float a = sc[r][jj] * invs;
            atomicAdd(r0 + lane + jj * 32, a * 0.2f);
            atomicAdd(rw + lane + jj * 32, a * wsh);
        }
    }
}

// =====================================================================
// 4a. gcnA: Ax partial over quarter K range (R15: BK=32, 2 barriers).
// =====================================================================
__global__ __launch_bounds__(160, 4)
void gcnA_kernel(const float* __restrict__ Asrc,
                 const float* __restrict__ Bsrc,
                 const float* __restrict__ sg1,
                 const float* __restrict__ sg2,
                 const float* __restrict__ Wx_b,
                 float* __restrict__ axout,
                 int mode) {
    __shared__ __align__(16) float As[2][32][36];
    __shared__ __align__(16) float Bs[2][32][104];

    int b  = blockIdx.z;
    int m0 = blockIdx.x * 32;
    int kh = blockIdx.y;
    int j0 = kh * 64;
    int tid = threadIdx.x;
    int tx = tid % 20, ty = tid / 20;
    int tx5 = tx * 5, ty4 = ty * 4;

    const float* Ab = Asrc + (long long)b * 65536;
    const float* Bb = Bsrc + (long long)b * (Ln * ATT);

    float sbb = 0.f;
    if (mode == 1) {
        #pragma unroll
        for (int kk2 = 0; kk2 < 5; kk2++) sbb += Wx_b[kk2];
    }

    int a0r = tid / 8, a0c = (tid % 8) * 4;
    int a1 = tid + 160;
    bool a1ok = (a1 < 256);
    int a1r = a1 / 8, a1c = (a1 % 8) * 4;
    int b0r = tid / 25, b0c = (tid % 25) * 4;
    int bi1 = tid + 160, b1r = bi1 / 25, b1c = (bi1 % 25) * 4;
    int bi2 = tid + 320, b2r = bi2 / 25, b2c = (bi2 % 25) * 4;
    int bi3 = tid + 480, b3r = bi3 / 25, b3c = (bi3 % 25) * 4;
    int bi4 = tid + 640, b4r = bi4 / 25, b4c = (bi4 % 25) * 4;

    float acc[4][5];
    #pragma unroll
    for (int i = 0; i < 4; i++)
        #pragma unroll
        for (int j = 0; j < 5; j++) acc[i][j] = 0.f;

    float4 aR0 = make_float4(0.f,0.f,0.f,0.f), aR1 = aR0;
    float4 bR0 = aR0, bR1 = aR0, bR2 = aR0, bR3 = aR0, bR4 = aR0;

    float sg2v0 = 0.f, sg2v1 = 0.f;
    if (mode == 1) {
        sg2v0 = sg2[b * 256 + m0 + a0r];
        if (a1ok) sg2v1 = sg2[b * 256 + m0 + a1r];
    }

    #define LOAD_A1(dst, rr, cc, sgv)                                           \
        do {                                                                    \
            float4 v_ = *reinterpret_cast<const float4*>(                       \
                Ab + (long long)(m0 + (rr)) * 256 + j0 + k0_ + (cc));           \
            if (mode == 0) {                                                    \
                dst = v_;                                                       \
            } else {                                                            \
                float4 s1_ = *reinterpret_cast<const float4*>(sg1 + b * 256 + j0 + k0_ + (cc)); \
                float c_ = sbb + (sgv);                                         \
                dst.x = 0.2f * (v_.x + c_ + s1_.x);                             \
                dst.y = 0.2f * (v_.y + c_ + s1_.y);                             \
                dst.z = 0.2f * (v_.z + c_ + s1_.z);                             \
                dst.w = 0.2f * (v_.w + c_ + s1_.w);                             \
            }                                                                   \
        } while (0)

    #define LOAD_AB(k0v)                                                        \
        do {                                                                    \
            int k0_ = (k0v);                                                    \
            LOAD_A1(aR0, a0r, a0c, sg2v0);                                      \
            if (a1ok) LOAD_A1(aR1, a1r, a1c, sg2v1);                            \
            bR0 = *reinterpret_cast<const float4*>(Bb + (long long)(j0 + k0_ + b0r) * ATT + b0c); \
            bR1 = *reinterpret_cast<const float4*>(Bb + (long long)(j0 + k0_ + b1r) * ATT + b1c); \
            bR2 = *reinterpret_cast<const float4*>(Bb + (long long)(j0 + k0_ + b2r) * ATT + b2c); \
            bR3 = *reinterpret_cast<const float4*>(Bb + (long long)(j0 + k0_ + b3r) * ATT + b3c); \
            bR4 = *reinterpret_cast<const float4*>(Bb + (long long)(j0 + k0_ + b4r) * ATT + b4c); \
        } while (0)

    LOAD_AB(0);

    int s = 0;
    for (int t = 0; t < 2; t++) {
        As[s][a0c + 0][a0r] = aR0.x;
        As[s][a0c + 1][a0r] = aR0.y;
        As[s][a0c + 2][a0r] = aR0.z;
        As[s][a0c + 3][a0r] = aR0.w;
        if (a1ok) {
            As[s][a1c + 0][a1r] = aR1.x;
            As[s][a1c + 1][a1r] = aR1.y;
            As[s][a1c + 2][a1r] = aR1.z;
            As[s][a1c + 3][a1r] = aR1.w;
        }
        *reinterpret_cast<float4*>(&Bs[s][b0r][b0c]) = bR0;
        *reinterpret_cast<float4*>(&Bs[s][b1r][b1c]) = bR1;
        *reinterpret_cast<float4*>(&Bs[s][b2r][b2c]) = bR2;
        *reinterpret_cast<float4*>(&Bs[s][b3r][b3c]) = bR3;
        *reinterpret_cast<float4*>(&Bs[s][b4r][b4c]) = bR4;
        __syncthreads();
        if (t + 1 < 2) LOAD_AB(32);
        #pragma unroll
        for (int kk = 0; kk < 32; kk++) {
            float4 a4 = *reinterpret_cast<const float4*>(&As[s][kk][ty4]);
            float b0 = Bs[s][kk][tx5 + 0];
            float b1 = Bs[s][kk][tx5 + 1];
            float b2 = Bs[s][kk][tx5 + 2];
            float b3 = Bs[s][kk][tx5 + 3];
            float b4 = Bs[s][kk][tx5 + 4];
            acc[0][0] += a4.x*b0; acc[0][1] += a4.x*b1; acc[0][2] += a4.x*b2; acc[0][3] += a4.x*b3; acc[0][4] += a4.x*b4;
            acc[1][0] += a4.y*b0; acc[1][1] += a4.y*b1; acc[1][2] += a4.y*b2; acc[1][3] += a4.y*b3; acc[1][4] += a4.y*b4;
            acc[2][0] += a4.z*b0; acc[2][1] += a4.z*b1; acc[2][2] += a4.z*b2; acc[2][3] += a4.z*b3; acc[2][4] += a4.z*b4;
            acc[3][0] += a4.w*b0; acc[3][1] += a4.w*b1; acc[3][2] += a4.w*b2; acc[3][3] += a4.w*b3; acc[3][4] += a4.w*b4;
        }
        s ^= 1;   // single-sync double buffering
    }
    #undef LOAD_A1
    #undef LOAD_AB

    float* axp = axout + (long long)kh * 819200;
    #pragma unroll
    for (int i = 0; i < 4; i++) {
        float* crow = axp + (long long)(b * 256 + m0 + ty4 + i) * ATT;
        #pragma unroll
        for (int j = 0; j < 5; j++) crow[tx5 + j] = acc[i][j];
    }
}

// =====================================================================
// 4b. gcnB: out = relu((ax0+ax1+ax2+ax3) @ W_w + W_b)  (R15 config)
// =====================================================================
__global__ __launch_bounds__(160, 4)
void gcnB_kernel(const float* __restrict__ ax,
                 const float* __restrict__ W_w,
                 const float* __restrict__ W_b,
                 const float* __restrict__ Wx_w,
                 const float* __restrict__ amask,
                 const float* __restrict__ clf_w,
                 float* __restrict__ outC,
                 float* __restrict__ sg1o,
                 float* __restrict__ sg2o,
                 float* __restrict__ out,
                 int mode) {
    __shared__ __align__(16) float As[2][20][36];
    __shared__ __align__(16) float Bs[2][20][104];
    __shared__ float smask[32];
    __shared__ float swn;

    int m0 = blockIdx.x * 32;
    int b = m0 >> 8;
    int tid = threadIdx.x;
    int tx = tid % 20, ty = tid / 20;
    int tx5 = tx * 5, ty4 = ty * 4;

    if (mode == 1) {
        if (tid < 32) smask[tid] = amask[b * Ln + (m0 & 255) + tid];
        if (tid >= 32 && tid < 64) {
            int lane = tid - 32;
            float sv = 0.f;
            for (int xx = lane; xx < Ln; xx += 32) sv += amask[b * Ln + xx];
            #pragma unroll
            for (int o = 16; o > 0; o >>= 1) sv += __shfl_xor_sync(0xffffffffu, sv, o);
            if (lane == 0) swn = 1.f / sv;
        }
    }

    int ar = tid / 5, ac = (tid % 5) * 4;
    int b0r = tid / 25, b0c = (tid % 25) * 4;
    int bi1 = tid + 160;
    int b1r = bi1 / 25, b1c = (bi1 % 25) * 4;
    int bi2 = tid + 320;
    int b2r = bi2 / 25, b2c = (bi2 % 25) * 4;
    int bi3 = tid + 480;
    bool b3ok = (bi3 < 500);
    int b3r = bi3 / 25, b3c = (bi3 % 25) * 4;

    float acc[4][5];
    #pragma unroll
    for (int i = 0; i < 4; i++)
        #pragma unroll
        for (int j = 0; j < 5; j++) acc[i][j] = 0.f;

    float4 aR, bR0, bR1, bR2, bR3 = make_float4(0.f,0.f,0.f,0.f);

    #define LOAD_A2(k0)                                                        \
        do {                                                                   \
            long long off_ = (long long)(m0 + ar) * ATT + (k0) + ac;           \
            float4 u0 = *reinterpret_cast<const float4*>(ax + off_);           \
            float4 u1 = *reinterpret_cast<const float4*>(ax + 819200 + off_);  \
            float4 u2 = *reinterpret_cast<const float4*>(ax + 1638400 + off_); \
            float4 u3 = *reinterpret_cast<const float4*>(ax + 2457600 + off_); \
            aR.x = (u0.x + u1.x) + (u2.x + u3.x);                              \
            aR.y = (u0.y + u1.y) + (u2.y + u3.y);                              \
            aR.z = (u0.z + u1.z) + (u2.z + u3.z);                              \
            aR.w = (u0.w + u1.w) + (u2.w + u3.w);                              \
        } while (0)

    #define LOAD_B2(k0)                                                        \
        do {                                                                   \
            bR0 = *reinterpret_cast<const float4*>(W_w + (long long)((k0) + b0r) * ATT + b0c); \
            bR1 = *reinterpret_cast<const float4*>(W_w + (long long)((k0) + b1r) * ATT + b1c); \
            bR2 = *reinterpret_cast<const float4*>(W_w + (long long)((k0) + b2r) * ATT + b2c); \
            if (b3ok) bR3 = *reinterpret_cast<const float4*>(W_w + (long long)((k0) + b3r) * ATT + b3c); \
        } while (0)

    LOAD_A2(0);
    LOAD_B2(0);

    int s = 0;
    for (int t = 0; t < 5; t++) {
        As[s][ac + 0][ar] = aR.x;
        As[s][ac + 1][ar] = aR.y;
        As[s][ac + 2][ar] = aR.z;
        As[s][ac + 3][ar] = aR.w;
        *reinterpret_cast<float4*>(&Bs[s][b0r][b0c]) = bR0;
        *reinterpret_cast<float4*>(&Bs[s][b1r][b1c]) = bR1;
        *reinterpret_cast<float4*>(&Bs[s][b2r][b2c]) = bR2;
        if (b3ok) *reinterpret_cast<float4*>(&Bs[s][b3r][b3c]) = bR3;
        __syncthreads();
        if (t + 1 < 5) {
            int k0 = (t + 1) * 20;
            LOAD_A2(k0);
            LOAD_B2(k0);
        }
        #pragma unroll
        for (int kk = 0; kk < 20; kk++) {
            float4 a4 = *reinterpret_cast<const float4*>(&As[s][kk][ty4]);
            float b0 = Bs[s][kk][tx5 + 0];
            float b1 = Bs[s][kk][tx5 + 1];
            float b2 = Bs[s][kk][tx5 + 2];
            float b3 = Bs[s][kk][tx5 + 3];
            float b4 = Bs[s][kk][tx5 + 4];
            acc[0][0] += a4.x*b0; acc[0][1] += a4.x*b1; acc[0][2] += a4.x*b2; acc[0][3] += a4.x*b3; acc[0][4] += a4.x*b4;
            acc[1][0] += a4.y*b0; acc[1][1] += a4.y*b1; acc[1][2] += a4.y*b2; acc[1][3] += a4.y*b3; acc[1][4] += a4.y*b4;
            acc[2][0] += a4.z*b0; acc[2][1] += a4.z*b1; acc[2][2] += a4.z*b2; acc[2][3] += a4.z*b3; acc[2][4] += a4.z*b4;
            acc[3][0] += a4.w*b0; acc[3][1] += a4.w*b1; acc[3][2] += a4.w*b2; acc[3][3] += a4.w*b3; acc[3][4] += a4.w*b4;
        }
        s ^= 1;
    }
    #undef LOAD_A2
    #undef LOAD_B2

    __syncthreads();

    float wb[5];
    #pragma unroll
    for (int j = 0; j < 5; j++) wb[j] = W_b[tx5 + j];

    if (mode == 0) {
        float w1r[5], w2r[5];
        #pragma unroll
        for (int j = 0; j < 5; j++) {
            float s1 = 0.f, s2 = 0.f;
            #pragma unroll
            for (int kk2 = 0; kk2 < 5; kk2++) {
                s1 += Wx_w[(5 + tx5 + j) * 5 + kk2];
                s2 += Wx_w[(105 + tx5 + j) * 5 + kk2];
            }
            w1r[j] = s1; w2r[j] = s2;
        }
        float p1[4] = {0.f,0.f,0.f,0.f}, p2[4] = {0.f,0.f,0.f,0.f};
        #pragma unroll
        for (int i = 0; i < 4; i++) {
            float* crow = outC + (long long)(m0 + ty4 + i) * ATT;
            #pragma unroll
            for (int j = 0; j < 5; j++) {
                float v = fmaxf(acc[i][j] + wb[j], 0.f);
                crow[tx5 + j] = v;
                p1[i] += v * w1r[j];
                p2[i] += v * w2r[j];
            }
        }
        float* red = &Bs[0][0][0];
        #pragma unroll
        for (int i = 0; i < 4; i++) {
            red[(ty4 + i) * 41 + tx]      = p1[i];
            red[(ty4 + i) * 41 + 20 + tx] = p2[i];
        }
        __syncthreads();
        if (tid < 32) {
            float s1 = 0.f, s2 = 0.f;
            #pragma unroll
            for (int xx = 0; xx < 20; xx++) { s1 += red[tid * 41 + xx]; s2 += red[tid * 41 + 20 + xx]; }
            sg1o[m0 + tid] = s1;
            sg2o[m0 + tid] = s2;
        }
    } else {
        float pv[5] = {0.f,0.f,0.f,0.f,0.f};
        #pragma unroll
        for (int i = 0; i < 4; i++) {
            float m = smask[ty4 + i];
            #pragma unroll
            for (int j = 0; j < 5; j++)
                pv[j] += fmaxf(acc[i][j] + wb[j], 0.f) * m;
        }
        float* pvred = &As[0][0][0];
        #pragma unroll
        for (int j = 0; j < 5; j++) pvred[ty * 101 + tx5 + j] = pv[j];
        __syncthreads();
        if (tid < ATT) {
            float s2 = 0.f;
            #pragma unroll
            for (int r = 0; r < 8; r++) s2 += pvred[r * 101 + tid];
            pvred[8 * 101 + tid] = s2;
        }
        __syncthreads();
        if (tid < 3) {
            float s2 = 0.f;
            for (int c = 0; c < ATT; c++) s2 += pvred[8 * 101 + c] * clf_w[c * 3 + tid];
            atomicAdd(out + b * 3 + tid, s2 * swn);
        }
    }
}

// ---------------- launch --------------------------------------------------
extern "C" void kernel_launch(void* const* d_in, const int* in_sizes, int n_in,
                              void* d_out, int out_size) {
    const float* seq     = (const float*)d_in[0];
    const int*   srcm    = (const int*)  d_in[1];
    const float* amask   = (const float*)d_in[2];
    const float* shortm  = (const float*)d_in[3];
    const float* ln_a    = (const float*)d_in[4];
    const float* ln_b    = (const float*)d_in[5];
    const float* Wxx_w   = (const float*)d_in[6];
    const float* Wxx_b   = (const float*)d_in[7];
    const float* q_w     = (const float*)d_in[8];
    const float* q_b     = (const float*)d_in[9];
    const float* k_w     = (const float*)d_in[10];
    const float* k_b     = (const float*)d_in[11];
    const float* dense_w = (const float*)d_in[12];
    const float* dense_b = (const float*)d_in[13];
    const float* bias_m  = (const float*)d_in[14];
    const float* W_w     = (const float*)d_in[15];
    const float* W_b     = (const float*)d_in[16];
    const float* Wx_w    = (const float*)d_in[17];
    const float* Wx_b    = (const float*)d_in[18];
    const float* clf_w   = (const float*)d_in[19];
    const float* clf_b   = (const float*)d_in[20];
    float* out = (float*)d_out;

    float* S = nullptr;
    cudaGetSymbolAddress((void**)&S, d_scratch);
    float* g     = S + OFF_G;
    float* q     = S + OFF_Q;
    float* k     = S + OFF_K;
    float* go    = S + OFF_GO;
    float* hs0   = S + OFF_HS0;
    float* hsw   = S + OFF_HSW;
    float* asp   = S + OFF_ASP;
    float* sg1   = S + OFF_SG1;
    float* sg2   = S + OFF_SG2;
    float* ax    = S + OFF_AX;

    // 0. zero the two h-reduced maps (one contiguous memset node)
    cudaMemsetAsync(hs0, 0, 2ll * Bn * Ln * Ln * sizeof(float));
    // 1. fused layernorm + g GEMM
    lng_kernel<<<NROW / 32, 320>>>(seq, ln_a, ln_b, Wxx_w, Wxx_b, g);
    // 2. q/k projections + aspect pooling
    qkaspect_kernel<<<288, 320>>>(g, q_w, q_b, k_w, k_b,
                                  amask, dense_w, dense_b, q, k, asp);
    // 3. scores + softmax -> atomic h-reduced maps hs0/hsw; inits out
    scores_kernel<<<dim3(Ln / 16, Hh, Bn), 256>>>(q, k, asp, bias_m, srcm, shortm,
                                                  Wx_w, clf_b, hs0, hsw, out);
    // 4. GCN layer 0: 4-way split-K Ax (BK=32), relu GEMM + sg1/sg2
    gcnA_kernel<<<dim3(8, 4, Bn), 160>>>(hs0, g, nullptr, nullptr, Wx_b, ax, 0);
    gcnB_kernel<<<NROW / 32, 160>>>(ax, W_w, W_b, Wx_w, amask, clf_w,
                                    go, sg1, sg2, out, 0);
    // 5. GCN layer 1: edge-collapsed Ax, relu GEMM + classifier
    gcnA_kernel<<<dim3(8, 4, Bn), 160>>>(hsw, go, sg1, sg2, Wx_b, ax, 1);
    gcnB_kernel<<<NROW / 32, 160>>>(ax, W_w, W_b, Wx_w, amask, clf_w,
                                    nullptr, nullptr, nullptr, out, 1);
}

// round 17
// speedup vs baseline: 1.3188x; 1.3188x over previous
#include <cuda_runtime.h>
#include <math.h>

// ---------------- problem constants ----------------
#define Bn   32
#define Ln   256
#define Dd   768
#define ATT  100
#define Hh   5
#define DK   20
#define NROW (Bn*Ln)            // 8192

// ---------------- scratch ----------------
#define OFF_G     6291456ll
#define OFF_Q     7110656ll
#define OFF_K     7929856ll
#define OFF_GO    8749056ll
#define OFF_HS0   11206656ll    // 32*256*256
#define OFF_HSW   13303808ll    // 32*256*256 (contiguous after HS0)
#define OFF_ASP   23792768ll    // 32*20
#define OFF_SG1   23834368ll    // 8192
#define OFF_SG2   23875328ll
#define OFF_AX    23916288ll    // 4 * 8192*100 partial Ax
#define SCRATCH_TOTAL 27193088ll

__device__ __align__(16) float d_scratch[SCRATCH_TOTAL];

// =====================================================================
// 1. Fused LayerNorm + GEMM:  g = LN(x) @ Wxx_w + Wxx_b  (R15 exact)
// =====================================================================
__global__ __launch_bounds__(320, 3)
void lng_kernel(const float* __restrict__ x,
                const float* __restrict__ ga,
                const float* __restrict__ gb,
                const float* __restrict__ Ww,
                const float* __restrict__ Wb,
                float* __restrict__ g) {
    __shared__ __align__(16) float As[2][16][36];
    __shared__ __align__(16) float Bs[2][16][104];
    __shared__ float smean[32], sinv[32];

    int tid = threadIdx.x;
    int m0 = blockIdx.x * 32;
    int w = tid >> 5, lane = tid & 31;

    if (w < 8) {
        #pragma unroll
        for (int r = 0; r < 4; r++) {
            int row = w * 4 + r;
            const float4* xr = reinterpret_cast<const float4*>(x + (long long)(m0 + row) * Dd);
            float sum = 0.f, sq = 0.f;
            #pragma unroll
            for (int i = 0; i < 6; i++) {
                float4 v = xr[lane + i * 32];
                sum += v.x + v.y + v.z + v.w;
                sq  += v.x*v.x + v.y*v.y + v.z*v.z + v.w*v.w;
            }
            #pragma unroll
            for (int o = 16; o > 0; o >>= 1) {
                sum += __shfl_xor_sync(0xffffffffu, sum, o);
                sq  += __shfl_xor_sync(0xffffffffu, sq,  o);
            }
            if (lane == 0) {
                float mean = sum * (1.f / (float)Dd);
                float var = (sq - (float)Dd * mean * mean) * (1.f / (float)(Dd - 1));
                smean[row] = mean;
                sinv[row] = 1.f / (sqrtf(var) + 1e-6f);
            }
        }
    }
    __syncthreads();

    int tx = tid % 20, ty = tid / 20;
    int tx5 = tx * 5, ty2 = ty * 2;

    bool aok = (tid < 128);
    int ar = tid >> 2, ac = (tid & 3) << 2;
    int b0r = tid / 25, b0c = (tid % 25) * 4;
    int bi1 = tid + 320;
    bool b1ok = (bi1 < 400);
    int b1r = bi1 / 25, b1c = (bi1 % 25) * 4;

    const float* Xrow = x + (long long)(m0 + ar) * Dd;
    float meanv = 0.f, invv = 0.f;
    if (aok) { meanv = smean[ar]; invv = sinv[ar]; }

    float acc[2][5];
    #pragma unroll
    for (int i = 0; i < 2; i++)
        #pragma unroll
        for (int j = 0; j < 5; j++) acc[i][j] = 0.f;

    float4 aR = make_float4(0.f,0.f,0.f,0.f), bR0 = aR, bR1 = aR;

    #define LOAD_LNA(k0)                                                 \
        do {                                                             \
            float4 x4 = *reinterpret_cast<const float4*>(Xrow + (k0) + ac);   \
            float4 ga4 = *reinterpret_cast<const float4*>(ga + (k0) + ac);    \
            float4 gb4 = *reinterpret_cast<const float4*>(gb + (k0) + ac);    \
            aR.x = ga4.x * (x4.x - meanv) * invv + gb4.x;                \
            aR.y = ga4.y * (x4.y - meanv) * invv + gb4.y;                \
            aR.z = ga4.z * (x4.z - meanv) * invv + gb4.z;                \
            aR.w = ga4.w * (x4.w - meanv) * invv + gb4.w;                \
        } while (0)

    if (aok) LOAD_LNA(0);
    bR0 = *reinterpret_cast<const float4*>(Ww + (long long)b0r * ATT + b0c);
    if (b1ok) bR1 = *reinterpret_cast<const float4*>(Ww + (long long)b1r * ATT + b1c);

    int s = 0;
    for (int t = 0; t < 48; t++) {
        if (aok) {
            As[s][ac + 0][ar] = aR.x;
            As[s][ac + 1][ar] = aR.y;
            As[s][ac + 2][ar] = aR.z;
            As[s][ac + 3][ar] = aR.w;
        }
        *reinterpret_cast<float4*>(&Bs[s][b0r][b0c]) = bR0;
        if (b1ok) *reinterpret_cast<float4*>(&Bs[s][b1r][b1c]) = bR1;
        __syncthreads();
        if (t + 1 < 48) {
            int k0 = (t + 1) * 16;
            if (aok) LOAD_LNA(k0);
            bR0 = *reinterpret_cast<const float4*>(Ww + (long long)(k0 + b0r) * ATT + b0c);
            if (b1ok) bR1 = *reinterpret_cast<const float4*>(Ww + (long long)(k0 + b1r) * ATT + b1c);
        }
        #pragma unroll
        for (int kk = 0; kk < 16; kk++) {
            float a0 = As[s][kk][ty2 + 0];
            float a1 = As[s][kk][ty2 + 1];
            float b0 = Bs[s][kk][tx5 + 0];
            float b1 = Bs[s][kk][tx5 + 1];
            float b2 = Bs[s][kk][tx5 + 2];
            float b3 = Bs[s][kk][tx5 + 3];
            float b4 = Bs[s][kk][tx5 + 4];
            acc[0][0] += a0*b0; acc[0][1] += a0*b1; acc[0][2] += a0*b2; acc[0][3] += a0*b3; acc[0][4] += a0*b4;
            acc[1][0] += a1*b0; acc[1][1] += a1*b1; acc[1][2] += a1*b2; acc[1][3] += a1*b3; acc[1][4] += a1*b4;
        }
        s ^= 1;
        __syncthreads();
    }
    #undef LOAD_LNA

    float wb[5];
    #pragma unroll
    for (int j = 0; j < 5; j++) wb[j] = Wb[tx5 + j];
    #pragma unroll
    for (int i = 0; i < 2; i++) {
        float* crow = g + (long long)(m0 + ty2 + i) * ATT;
        #pragma unroll
        for (int j = 0; j < 5; j++) crow[tx5 + j] = acc[i][j] + wb[j];
    }
}

// =====================================================================
// 2. Merged: q/k projections + aspect pooling (R15 exact)
// =====================================================================
__global__ __launch_bounds__(320, 2)
void qkaspect_kernel(const float* __restrict__ g,
                     const float* __restrict__ q_w, const float* __restrict__ q_b,
                     const float* __restrict__ k_w, const float* __restrict__ k_b,
                     const float* __restrict__ amask,
                     const float* __restrict__ dense_w,
                     const float* __restrict__ dense_b,
                     float* __restrict__ q, float* __restrict__ k,
                     float* __restrict__ asp) {
    int blk = blockIdx.x;
    int tid = threadIdx.x;

    if (blk < 256) {
        __shared__ __align__(16) float As[2][20][68];
        __shared__ __align__(16) float Bs[2][20][104];

        const float* Bw; const float* bias; float* C;
        if (blk < 128) { Bw = q_w; bias = q_b; C = q; }
        else           { Bw = k_w; bias = k_b; C = k; }
        int m0 = (blk & 127) * 64;

        int tx = tid % 20, ty = tid / 20;
        int tx5 = tx * 5, ty4 = ty * 4;

        int ar = tid / 5, ac = (tid % 5) * 4;
        int b0r = tid / 25, b0c = (tid % 25) * 4;
        int bi1 = tid + 320;
        bool b1ok = (bi1 < 500);
        int b1r = bi1 / 25, b1c = (bi1 % 25) * 4;

        const float* Arow = g + (long long)(m0 + ar) * ATT;

        float acc[4][5];
        #pragma unroll
        for (int i = 0; i < 4; i++)
            #pragma unroll
            for (int j = 0; j < 5; j++) acc[i][j] = 0.f;

        float4 aR, bR0, bR1 = make_float4(0.f,0.f,0.f,0.f);
        aR = *reinterpret_cast<const float4*>(Arow + ac);
        bR0 = *reinterpret_cast<const float4*>(Bw + (long long)b0r * ATT + b0c);
        if (b1ok) bR1 = *reinterpret_cast<const float4*>(Bw + (long long)b1r * ATT + b1c);

        int s = 0;
        for (int t = 0; t < 5; t++) {
            As[s][ac + 0][ar] = aR.x;
            As[s][ac + 1][ar] = aR.y;
            As[s][ac + 2][ar] = aR.z;
            As[s][ac + 3][ar] = aR.w;
            *reinterpret_cast<float4*>(&Bs[s][b0r][b0c]) = bR0;
            if (b1ok) *reinterpret_cast<float4*>(&Bs[s][b1r][b1c]) = bR1;
            __syncthreads();
            if (t + 1 < 5) {
                int k0 = (t + 1) * 20;
                aR = *reinterpret_cast<const float4*>(Arow + k0 + ac);
                bR0 = *reinterpret_cast<const float4*>(Bw + (long long)(k0 + b0r) * ATT + b0c);
                if (b1ok) bR1 = *reinterpret_cast<const float4*>(Bw + (long long)(k0 + b1r) * ATT + b1c);
            }
            #pragma unroll
            for (int kk = 0; kk < 20; kk++) {
                float4 a4 = *reinterpret_cast<const float4*>(&As[s][kk][ty4]);
                float b0 = Bs[s][kk][tx5 + 0];
                float b1 = Bs[s][kk][tx5 + 1];
                float b2 = Bs[s][kk][tx5 + 2];
                float b3 = Bs[s][kk][tx5 + 3];
                float b4 = Bs[s][kk][tx5 + 4];
                acc[0][0] += a4.x*b0; acc[0][1] += a4.x*b1; acc[0][2] += a4.x*b2; acc[0][3] += a4.x*b3; acc[0][4] += a4.x*b4;
                acc[1][0] += a4.y*b0; acc[1][1] += a4.y*b1; acc[1][2] += a4.y*b2; acc[1][3] += a4.y*b3; acc[1][4] += a4.y*b4;
                acc[2][0] += a4.z*b0; acc[2][1] += a4.z*b1; acc[2][2] += a4.z*b2; acc[2][3] += a4.z*b3; acc[2][4] += a4.z*b4;
                acc[3][0] += a4.w*b0; acc[3][1] += a4.w*b1; acc[3][2] += a4.w*b2; acc[3][3] += a4.w*b3; acc[3][4] += a4.w*b4;
            }
            s ^= 1;
            __syncthreads();
        }

        float wb[5];
        #pragma unroll
        for (int j = 0; j < 5; j++) wb[j] = bias[tx5 + j];
        #pragma unroll
        for (int i = 0; i < 4; i++) {
            float* crow = C + (long long)(m0 + ty4 + i) * ATT;
            #pragma unroll
            for (int j = 0; j < 5; j++) crow[tx5 + j] = acc[i][j] + wb[j];
        }
    } else {
        int b = blk - 256;
        int w = tid >> 5, lane = tid & 31;
        __shared__ float smask[Ln];
        __shared__ float part[8][104];
        __shared__ float sa[104];
        __shared__ float wred[8];

        if (tid < 256) smask[tid] = amask[b * Ln + tid];
        __syncthreads();

        if (w < 8) {
            float acc[4] = {0.f, 0.f, 0.f, 0.f};
            float wsum = 0.f;
            const float* gb_ = g + (long long)b * Ln * ATT;
            for (int i = w * 32; i < w * 32 + 32; i++) {
                float m = smask[i];
                wsum += m;
                const float* gr = gb_ + (long long)i * ATT;
                #pragma unroll
                for (int c4 = 0; c4 < 4; c4++) {
                    int c = lane + c4 * 32;
                    float gv = (c < ATT) ? gr[c] : 0.f;
                    acc[c4] += gv * m;
                }
            }
            #pragma unroll
            for (int c4 = 0; c4 < 4; c4++) {
                int c = lane + c4 * 32;
                if (c < ATT) part[w][c] = acc[c4];
            }
            if (lane == 0) wred[w] = wsum;
        }
        __syncthreads();
        if (tid < ATT) {
            float s = 0.f;
            #pragma unroll
            for (int ww = 0; ww < 8; ww++) s += part[ww][tid];
            sa[tid] = s;
        }
        if (tid == 0) {
            float s = 0.f;
            #pragma unroll
            for (int ww = 0; ww < 8; ww++) s += wred[ww];
            wred[0] = 1.f / s;
        }
        __syncthreads();
        float inv = wred[0];
        if (tid < DK) {
            float s = dense_b[tid];
            for (int c = 0; c < ATT; c++) s += sa[c] * inv * dense_w[c * DK + tid];
            asp[b * DK + tid] = s;
        }
    }
}

// =====================================================================
// 3. scores: 16 rows/CTA, per-(b,h), atomic h-reduced maps.
//    R15 structure (two barriers, smem-based addv) with ONE change:
//    src_mask penalty folded into addv (msk smem + inner predicate gone).
// =====================================================================
__global__ __launch_bounds__(256, 4)
void scores_kernel(const float* __restrict__ q,
                   const float* __restrict__ k,
                   const float* __restrict__ asp,
                   const float* __restrict__ bias_m,
                   const int*   __restrict__ src_mask,
                   const float* __restrict__ short_mask,
                   const float* __restrict__ Wx_w,
                   const float* __restrict__ clf_b,
                   float* __restrict__ hs0,
                   float* __restrict__ hsw,
                   float* __restrict__ out) {
    int it = blockIdx.x, h = blockIdx.y, b = blockIdx.z;
    __shared__ float kt[Ln][21];
    __shared__ float addv[Ln];
    __shared__ float qs[16][20];
    __shared__ float sasp[DK];
    int t = threadIdx.x, w = t >> 5, lane = t & 31;
    int i0 = it * 16 + w * 2;

    if (it == 0 && h == 0 && t < 3) out[b * 3 + t] = clf_b[t];

    if (t < DK) sasp[t] = asp[b * DK + t];
    {
        const float4* kr = reinterpret_cast<const float4*>(
            k + ((long long)b * Ln + t) * ATT + h * DK);
        #pragma unroll
        for (int f = 0; f < 5; f++) {
            float4 v = kr[f];
            kt[t][f * 4 + 0] = v.x;
            kt[t][f * 4 + 1] = v.y;
            kt[t][f * 4 + 2] = v.z;
            kt[t][f * 4 + 3] = v.w;
        }
    }
    for (int idx = t; idx < 16 * DK; idx += 256) {
        int r = idx / DK, d = idx % DK;
        qs[r][d] = q[((long long)b * Ln + it * 16 + r) * ATT + h * DK + d];
    }
    __syncthreads();
    {
        float s = 0.f;
        #pragma unroll
        for (int d = 0; d < DK; d++) s += sasp[d] * kt[t][d];
        float mpen = (src_mask[b * Ln + t] == 0) ? -1e9f : 0.f;
        addv[t] = tanhf(s + bias_m[0]) + mpen;
    }
    __syncthreads();

    float wsh = 0.f;
    #pragma unroll
    for (int kk = 0; kk < 5; kk++) wsh += Wx_w[h * 5 + kk];

    float smr[2][8];
    #pragma unroll
    for (int r = 0; r < 2; r++) {
        const float* srow = short_mask + ((long long)b * Ln + i0 + r) * Ln;
        #pragma unroll
        for (int jj = 0; jj < 8; jj++) smr[r][jj] = srow[lane + jj * 32];
    }

    float sc[2][8];
    #pragma unroll
    for (int r = 0; r < 2; r++)
        #pragma unroll
        for (int jj = 0; jj < 8; jj++) sc[r][jj] = 0.f;

    #pragma unroll
    for (int d = 0; d < DK; d++) {
        float qd0 = qs[w * 2 + 0][d];
        float qd1 = qs[w * 2 + 1][d];
        #pragma unroll
        for (int jj = 0; jj < 8; jj++) {
            float kv = kt[lane + jj * 32][d];
            sc[0][jj] += qd0 * kv;
            sc[1][jj] += qd1 * kv;
        }
    }

    const float rsd = 0.22360679774997896f;
    #pragma unroll
    for (int r = 0; r < 2; r++) {
        float mx = -3.4e38f;
        #pragma unroll
        for (int jj = 0; jj < 8; jj++) {
            int j = lane + jj * 32;
            float v = sc[r][jj] * rsd + addv[j] + smr[r][jj];
            sc[r][jj] = v;
            mx = fmaxf(mx, v);
        }
        #pragma unroll
        for (int o = 16; o > 0; o >>= 1) mx = fmaxf(mx, __shfl_xor_sync(0xffffffffu, mx, o));
        float sum = 0.f;
        #pragma unroll
        for (int jj = 0; jj < 8; jj++) { sc[r][jj] = expf(sc[r][jj] - mx); sum += sc[r][jj]; }
        #pragma unroll
        for (int o = 16; o > 0; o >>= 1) sum += __shfl_xor_sync(0xffffffffu, sum, o);
        float invs = 1.f / sum;
        float* r0 = hs0 + ((long long)b * Ln + i0 + r) * Ln;
        float* rw = hsw + ((long long)b * Ln + i0 + r) * Ln;
        #pragma unroll
        for (int jj = 0; jj < 8; jj++) {
            float a = sc[r][jj] * invs;
            atomicAdd(r0 + lane + jj * 32, a * 0.2f);
            atomicAdd(rw + lane + jj * 32, a * wsh);
        }
    }
}

// =====================================================================
// 4a. gcnA: Ax partial over quarter K range (R15 exact: BK=32).
// =====================================================================
__global__ __launch_bounds__(160, 4)
void gcnA_kernel(const float* __restrict__ Asrc,
                 const float* __restrict__ Bsrc,
                 const float* __restrict__ sg1,
                 const float* __restrict__ sg2,
                 const float* __restrict__ Wx_b,
                 float* __restrict__ axout,
                 int mode) {
    __shared__ __align__(16) float As[2][32][36];
    __shared__ __align__(16) float Bs[2][32][104];

    int b  = blockIdx.z;
    int m0 = blockIdx.x * 32;
    int kh = blockIdx.y;
    int j0 = kh * 64;
    int tid = threadIdx.x;
    int tx = tid % 20, ty = tid / 20;
    int tx5 = tx * 5, ty4 = ty * 4;

    const float* Ab = Asrc + (long long)b * 65536;
    const float* Bb = Bsrc + (long long)b * (Ln * ATT);

    float sbb = 0.f;
    if (mode == 1) {
        #pragma unroll
        for (int kk2 = 0; kk2 < 5; kk2++) sbb += Wx_b[kk2];
    }

    int a0r = tid / 8, a0c = (tid % 8) * 4;
    int a1 = tid + 160;
    bool a1ok = (a1 < 256);
    int a1r = a1 / 8, a1c = (a1 % 8) * 4;
    int b0r = tid / 25, b0c = (tid % 25) * 4;
    int bi1 = tid + 160, b1r = bi1 / 25, b1c = (bi1 % 25) * 4;
    int bi2 = tid + 320, b2r = bi2 / 25, b2c = (bi2 % 25) * 4;
    int bi3 = tid + 480, b3r = bi3 / 25, b3c = (bi3 % 25) * 4;
    int bi4 = tid + 640, b4r = bi4 / 25, b4c = (bi4 % 25) * 4;

    float acc[4][5];
    #pragma unroll
    for (int i = 0; i < 4; i++)
        #pragma unroll
        for (int j = 0; j < 5; j++) acc[i][j] = 0.f;

    float4 aR0 = make_float4(0.f,0.f,0.f,0.f), aR1 = aR0;
    float4 bR0 = aR0, bR1 = aR0, bR2 = aR0, bR3 = aR0, bR4 = aR0;

    float sg2v0 = 0.f, sg2v1 = 0.f;
    if (mode == 1) {
        sg2v0 = sg2[b * 256 + m0 + a0r];
        if (a1ok) sg2v1 = sg2[b * 256 + m0 + a1r];
    }

    #define LOAD_A1(dst, rr, cc, sgv)                                           \
        do {                                                                    \
            float4 v_ = *reinterpret_cast<const float4*>(                       \
                Ab + (long long)(m0 + (rr)) * 256 + j0 + k0_ + (cc));           \
            if (mode == 0) {                                                    \
                dst = v_;                                                       \
            } else {                                                            \
                float4 s1_ = *reinterpret_cast<const float4*>(sg1 + b * 256 + j0 + k0_ + (cc)); \
                float c_ = sbb + (sgv);                                         \
                dst.x = 0.2f * (v_.x + c_ + s1_.x);                             \
                dst.y = 0.2f * (v_.y + c_ + s1_.y);                             \
                dst.z = 0.2f * (v_.z + c_ + s1_.z);                             \
                dst.w = 0.2f * (v_.w + c_ + s1_.w);                             \
            }                                                                   \
        } while (0)

    #define LOAD_AB(k0v)                                                        \
        do {                                                                    \
            int k0_ = (k0v);                                                    \
            LOAD_A1(aR0, a0r, a0c, sg2v0);                                      \
            if (a1ok) LOAD_A1(aR1, a1r, a1c, sg2v1);                            \
            bR0 = *reinterpret_cast<const float4*>(Bb + (long long)(j0 + k0_ + b0r) * ATT + b0c); \
            bR1 = *reinterpret_cast<const float4*>(Bb + (long long)(j0 + k0_ + b1r) * ATT + b1c); \
            bR2 = *reinterpret_cast<const float4*>(Bb + (long long)(j0 + k0_ + b2r) * ATT + b2c); \
            bR3 = *reinterpret_cast<const float4*>(Bb + (long long)(j0 + k0_ + b3r) * ATT + b3c); \
            bR4 = *reinterpret_cast<const float4*>(Bb + (long long)(j0 + k0_ + b4r) * ATT + b4c); \
        } while (0)

    LOAD_AB(0);

    int s = 0;
    for (int t = 0; t < 2; t++) {
        As[s][a0c + 0][a0r] = aR0.x;
        As[s][a0c + 1][a0r] = aR0.y;
        As[s][a0c + 2][a0r] = aR0.z;
        As[s][a0c + 3][a0r] = aR0.w;
        if (a1ok) {
            As[s][a1c + 0][a1r] = aR1.x;
            As[s][a1c + 1][a1r] = aR1.y;
            As[s][a1c + 2][a1r] = aR1.z;
            As[s][a1c + 3][a1r] = aR1.w;
        }
        *reinterpret_cast<float4*>(&Bs[s][b0r][b0c]) = bR0;
        *reinterpret_cast<float4*>(&Bs[s][b1r][b1c]) = bR1;
        *reinterpret_cast<float4*>(&Bs[s][b2r][b2c]) = bR2;
        *reinterpret_cast<float4*>(&Bs[s][b3r][b3c]) = bR3;
        *reinterpret_cast<float4*>(&Bs[s][b4r][b4c]) = bR4;
        __syncthreads();
        if (t + 1 < 2) LOAD_AB(32);
        #pragma unroll
        for (int kk = 0; kk < 32; kk++) {
            float4 a4 = *reinterpret_cast<const float4*>(&As[s][kk][ty4]);
            float b0 = Bs[s][kk][tx5 + 0];
            float b1 = Bs[s][kk][tx5 + 1];
            float b2 = Bs[s][kk][tx5 + 2];
            float b3 = Bs[s][kk][tx5 + 3];
            float b4 = Bs[s][kk][tx5 + 4];
            acc[0][0] += a4.x*b0; acc[0][1] += a4.x*b1; acc[0][2] += a4.x*b2; acc[0][3] += a4.x*b3; acc[0][4] += a4.x*b4;
            acc[1][0] += a4.y*b0; acc[1][1] += a4.y*b1; acc[1][2] += a4.y*b2; acc[1][3] += a4.y*b3; acc[1][4] += a4.y*b4;
            acc[2][0] += a4.z*b0; acc[2][1] += a4.z*b1; acc[2][2] += a4.z*b2; acc[2][3] += a4.z*b3; acc[2][4] += a4.z*b4;
            acc[3][0] += a4.w*b0; acc[3][1] += a4.w*b1; acc[3][2] += a4.w*b2; acc[3][3] += a4.w*b3; acc[3][4] += a4.w*b4;
        }
        s ^= 1;   // single-sync double buffering
    }
    #undef LOAD_A1
    #undef LOAD_AB

    float* axp = axout + (long long)kh * 819200;
    #pragma unroll
    for (int i = 0; i < 4; i++) {
        float* crow = axp + (long long)(b * 256 + m0 + ty4 + i) * ATT;
        #pragma unroll
        for (int j = 0; j < 5; j++) crow[tx5 + j] = acc[i][j];
    }
}

// =====================================================================
// 4b. gcnB: out = relu((ax0+ax1+ax2+ax3) @ W_w + W_b)  (R15 exact)
// =====================================================================
__global__ __launch_bounds__(160, 4)
void gcnB_kernel(const float* __restrict__ ax,
                 const float* __restrict__ W_w,
                 const float* __restrict__ W_b,
                 const float* __restrict__ Wx_w,
                 const float* __restrict__ amask,
                 const float* __restrict__ clf_w,
                 float* __restrict__ outC,
                 float* __restrict__ sg1o,
                 float* __restrict__ sg2o,
                 float* __restrict__ out,
                 int mode) {
    __shared__ __align__(16) float As[2][20][36];
    __shared__ __align__(16) float Bs[2][20][104];
    __shared__ float smask[32];
    __shared__ float swn;

    int m0 = blockIdx.x * 32;
    int b = m0 >> 8;
    int tid = threadIdx.x;
    int tx = tid % 20, ty = tid / 20;
    int tx5 = tx * 5, ty4 = ty * 4;

    if (mode == 1) {
        if (tid < 32) smask[tid] = amask[b * Ln + (m0 & 255) + tid];
        if (tid >= 32 && tid < 64) {
            int lane = tid - 32;
            float sv = 0.f;
            for (int xx = lane; xx < Ln; xx += 32) sv += amask[b * Ln + xx];
            #pragma unroll
            for (int o = 16; o > 0; o >>= 1) sv += __shfl_xor_sync(0xffffffffu, sv, o);
            if (lane == 0) swn = 1.f / sv;
        }
    }

    int ar = tid / 5, ac = (tid % 5) * 4;
    int b0r = tid / 25, b0c = (tid % 25) * 4;
    int bi1 = tid + 160;
    int b1r = bi1 / 25, b1c = (bi1 % 25) * 4;
    int bi2 = tid + 320;
    int b2r = bi2 / 25, b2c = (bi2 % 25) * 4;
    int bi3 = tid + 480;
    bool b3ok = (bi3 < 500);
    int b3r = bi3 / 25, b3c = (bi3 % 25) * 4;

    float acc[4][5];
    #pragma unroll
    for (int i = 0; i < 4; i++)
        #pragma unroll
        for (int j = 0; j < 5; j++) acc[i][j] = 0.f;

    float4 aR, bR0, bR1, bR2, bR3 = make_float4(0.f,0.f,0.f,0.f);

    #define LOAD_A2(k0)                                                        \
        do {                                                                   \
            long long off_ = (long long)(m0 + ar) * ATT + (k0) + ac;           \
            float4 u0 = *reinterpret_cast<const float4*>(ax + off_);           \
            float4 u1 = *reinterpret_cast<const float4*>(ax + 819200 + off_);  \
            float4 u2 = *reinterpret_cast<const float4*>(ax + 1638400 + off_); \
            float4 u3 = *reinterpret_cast<const float4*>(ax + 2457600 + off_); \
            aR.x = (u0.x + u1.x) + (u2.x + u3.x);                              \
            aR.y = (u0.y + u1.y) + (u2.y + u3.y);                              \
            aR.z = (u0.z + u1.z) + (u2.z + u3.z);                              \
            aR.w = (u0.w + u1.w) + (u2.w + u3.w);                              \
        } while (0)

    #define LOAD_B2(k0)                                                        \
        do {                                                                   \
            bR0 = *reinterpret_cast<const float4*>(W_w + (long long)((k0) + b0r) * ATT + b0c); \
            bR1 = *reinterpret_cast<const float4*>(W_w + (long long)((k0) + b1r) * ATT + b1c); \
            bR2 = *reinterpret_cast<const float4*>(W_w + (long long)((k0) + b2r) * ATT + b2c); \
            if (b3ok) bR3 = *reinterpret_cast<const float4*>(W_w + (long long)((k0) + b3r) * ATT + b3c); \
        } while (0)

    LOAD_A2(0);
    LOAD_B2(0);

    int s = 0;
    for (int t = 0; t < 5; t++) {
        As[s][ac + 0][ar] = aR.x;
        As[s][ac + 1][ar] = aR.y;
        As[s][ac + 2][ar] = aR.z;
        As[s][ac + 3][ar] = aR.w;
        *reinterpret_cast<float4*>(&Bs[s][b0r][b0c]) = bR0;
        *reinterpret_cast<float4*>(&Bs[s][b1r][b1c]) = bR1;
        *reinterpret_cast<float4*>(&Bs[s][b2r][b2c]) = bR2;
        if (b3ok) *reinterpret_cast<float4*>(&Bs[s][b3r][b3c]) = bR3;
        __syncthreads();
        if (t + 1 < 5) {
            int k0 = (t + 1) * 20;
            LOAD_A2(k0);
            LOAD_B2(k0);
        }
        #pragma unroll
        for (int kk = 0; kk < 20; kk++) {
            float4 a4 = *reinterpret_cast<const float4*>(&As[s][kk][ty4]);
            float b0 = Bs[s][kk][tx5 + 0];
            float b1 = Bs[s][kk][tx5 + 1];
            float b2 = Bs[s][kk][tx5 + 2];
            float b3 = Bs[s][kk][tx5 + 3];
            float b4 = Bs[s][kk][tx5 + 4];
            acc[0][0] += a4.x*b0; acc[0][1] += a4.x*b1; acc[0][2] += a4.x*b2; acc[0][3] += a4.x*b3; acc[0][4] += a4.x*b4;
            acc[1][0] += a4.y*b0; acc[1][1] += a4.y*b1; acc[1][2] += a4.y*b2; acc[1][3] += a4.y*b3; acc[1][4] += a4.y*b4;
            acc[2][0] += a4.z*b0; acc[2][1] += a4.z*b1; acc[2][2] += a4.z*b2; acc[2][3] += a4.z*b3; acc[2][4] += a4.z*b4;
            acc[3][0] += a4.w*b0; acc[3][1] += a4.w*b1; acc[3][2] += a4.w*b2; acc[3][3] += a4.w*b3; acc[3][4] += a4.w*b4;
        }
        s ^= 1;
    }
    #undef LOAD_A2
    #undef LOAD_B2

    __syncthreads();

    float wb[5];
    #pragma unroll
    for (int j = 0; j < 5; j++) wb[j] = W_b[tx5 + j];

    if (mode == 0) {
        float w1r[5], w2r[5];
        #pragma unroll
        for (int j = 0; j < 5; j++) {
            float s1 = 0.f, s2 = 0.f;
            #pragma unroll
            for (int kk2 = 0; kk2 < 5; kk2++) {
                s1 += Wx_w[(5 + tx5 + j) * 5 + kk2];
                s2 += Wx_w[(105 + tx5 + j) * 5 + kk2];
            }
            w1r[j] = s1; w2r[j] = s2;
        }
        float p1[4] = {0.f,0.f,0.f,0.f}, p2[4] = {0.f,0.f,0.f,0.f};
        #pragma unroll
        for (int i = 0; i < 4; i++) {
            float* crow = outC + (long long)(m0 + ty4 + i) * ATT;
            #pragma unroll
            for (int j = 0; j < 5; j++) {
                float v = fmaxf(acc[i][j] + wb[j], 0.f);
                crow[tx5 + j] = v;
                p1[i] += v * w1r[j];
                p2[i] += v * w2r[j];
            }
        }
        float* red = &Bs[0][0][0];
        #pragma unroll
        for (int i = 0; i < 4; i++) {
            red[(ty4 + i) * 41 + tx]      = p1[i];
            red[(ty4 + i) * 41 + 20 + tx] = p2[i];
        }
        __syncthreads();
        if (tid < 32) {
            float s1 = 0.f, s2 = 0.f;
            #pragma unroll
            for (int xx = 0; xx < 20; xx++) { s1 += red[tid * 41 + xx]; s2 += red[tid * 41 + 20 + xx]; }
            sg1o[m0 + tid] = s1;
            sg2o[m0 + tid] = s2;
        }
    } else {
        float pv[5] = {0.f,0.f,0.f,0.f,0.f};
        #pragma unroll
        for (int i = 0; i < 4; i++) {
            float m = smask[ty4 + i];
            #pragma unroll
            for (int j = 0; j < 5; j++)
                pv[j] += fmaxf(acc[i][j] + wb[j], 0.f) * m;
        }
        float* pvred = &As[0][0][0];
        #pragma unroll
        for (int j = 0; j < 5; j++) pvred[ty * 101 + tx5 + j] = pv[j];
        __syncthreads();
        if (tid < ATT) {
            float s2 = 0.f;
            #pragma unroll
            for (int r = 0; r < 8; r++) s2 += pvred[r * 101 + tid];
            pvred[8 * 101 + tid] = s2;
        }
        __syncthreads();
        if (tid < 3) {
            float s2 = 0.f;
            for (int c = 0; c < ATT; c++) s2 += pvred[8 * 101 + c] * clf_w[c * 3 + tid];
            atomicAdd(out + b * 3 + tid, s2 * swn);
        }
    }
}

// ---------------- launch --------------------------------------------------
extern "C" void kernel_launch(void* const* d_in, const int* in_sizes, int n_in,
                              void* d_out, int out_size) {
    const float* seq     = (const float*)d_in[0];
    const int*   srcm    = (const int*)  d_in[1];
    const float* amask   = (const float*)d_in[2];
    const float* shortm  = (const float*)d_in[3];
    const float* ln_a    = (const float*)d_in[4];
    const float* ln_b    = (const float*)d_in[5];
    const float* Wxx_w   = (const float*)d_in[6];
    const float* Wxx_b   = (const float*)d_in[7];
    const float* q_w     = (const float*)d_in[8];
    const float* q_b     = (const float*)d_in[9];
    const float* k_w     = (const float*)d_in[10];
    const float* k_b     = (const float*)d_in[11];
    const float* dense_w = (const float*)d_in[12];
    const float* dense_b = (const float*)d_in[13];
    const float* bias_m  = (const float*)d_in[14];
    const float* W_w     = (const float*)d_in[15];
    const float* W_b     = (const float*)d_in[16];
    const float* Wx_w    = (const float*)d_in[17];
    const float* Wx_b    = (const float*)d_in[18];
    const float* clf_w   = (const float*)d_in[19];
    const float* clf_b   = (const float*)d_in[20];
    float* out = (float*)d_out;

    float* S = nullptr;
    cudaGetSymbolAddress((void**)&S, d_scratch);
    float* g     = S + OFF_G;
    float* q     = S + OFF_Q;
    float* k     = S + OFF_K;
    float* go    = S + OFF_GO;
    float* hs0   = S + OFF_HS0;
    float* hsw   = S + OFF_HSW;
    float* asp   = S + OFF_ASP;
    float* sg1   = S + OFF_SG1;
    float* sg2   = S + OFF_SG2;
    float* ax    = S + OFF_AX;

    // 0. zero the two h-reduced maps (one contiguous memset node)
    cudaMemsetAsync(hs0, 0, 2ll * Bn * Ln * Ln * sizeof(float));
    // 1. fused layernorm + g GEMM
    lng_kernel<<<NROW / 32, 320>>>(seq, ln_a, ln_b, Wxx_w, Wxx_b, g);
    // 2. q/k projections + aspect pooling
    qkaspect_kernel<<<288, 320>>>(g, q_w, q_b, k_w, k_b,
                                  amask, dense_w, dense_b, q, k, asp);
    // 3. scores + softmax -> atomic h-reduced maps hs0/hsw; inits out
    scores_kernel<<<dim3(Ln / 16, Hh, Bn), 256>>>(q, k, asp, bias_m, srcm, shortm,
                                                  Wx_w, clf_b, hs0, hsw, out);
    // 4. GCN layer 0: 4-way split-K Ax (BK=32), relu GEMM + sg1/sg2
    gcnA_kernel<<<dim3(8, 4, Bn), 160>>>(hs0, g, nullptr, nullptr, Wx_b, ax, 0);
    gcnB_kernel<<<NROW / 32, 160>>>(ax, W_w, W_b, Wx_w, amask, clf_w,
                                    go, sg1, sg2, out, 0);
    // 5. GCN layer 1: edge-collapsed Ax, relu GEMM + classifier
    gcnA_kernel<<<dim3(8, 4, Bn), 160>>>(hsw, go, sg1, sg2, Wx_b, ax, 1);
    gcnB_kernel<<<NROW / 32, 160>>>(ax, W_w, W_b, Wx_w, amask, clf_w,
                                    nullptr, nullptr, nullptr, out, 1);
}